// round 7
// baseline (speedup 1.0000x reference)
#include <cuda_runtime.h>
#include <cuda_bf16.h>
#include <cuda_fp16.h>
#include <cstdint>

// ---------------- problem constants ----------------
static constexpr int NB  = 16;
static constexpr int SEQ = 2048;
static constexpr int DIM = 128;
static constexpr size_t NEL = (size_t)NB * SEQ * DIM;   // 4,194,304

// BLOCK_M=128 (8 warps x 16 rows), BLOCK_N=64, 32 iters, 3-stage ring
static constexpr int BLK_N   = 64;
static constexpr int NIT     = SEQ / BLK_N;             // 32
static constexpr uint32_t ROWB    = 272;                // 256B data + 16B pad (conflict-free ldmatrix)
static constexpr uint32_t TILE_B  = 64 * ROWB;          // 17408
static constexpr uint32_t STAGE_B = 3 * TILE_B;         // Khi, Klo, Vh = 52224
static constexpr uint32_t SMEM_BYTES = 3 * STAGE_B;     // 156672 (3-stage ring)

// ---------------- static device scratch (no allocs) ----------------
__device__ __align__(256) __nv_bfloat16 g_Khi[NEL];
__device__ __align__(256) __nv_bfloat16 g_Klo[NEL];
__device__ __align__(256) __half        g_Vh [NEL];

// ---------------- PTX helpers (base compute_103) ----------------
__device__ __forceinline__ uint32_t smem_u32(const void* p) {
    uint32_t a;
    asm("{ .reg .u64 t; cvta.to.shared.u64 t, %1; cvt.u32.u64 %0, t; }" : "=r"(a) : "l"(p));
    return a;
}
#define CP16(sm, gp) asm volatile("cp.async.cg.shared.global [%0], [%1], 16;" :: "r"(sm), "l"(gp))
#define CP_COMMIT()  asm volatile("cp.async.commit_group;" ::: "memory")
#define CP_WAIT1()   asm volatile("cp.async.wait_group 1;" ::: "memory")
#define CP_WAIT0()   asm volatile("cp.async.wait_group 0;" ::: "memory")

__device__ __forceinline__ void ldm_x4(uint32_t* r, uint32_t addr) {
    asm volatile("ldmatrix.sync.aligned.m8n8.x4.shared.b16 {%0,%1,%2,%3}, [%4];"
                 : "=r"(r[0]), "=r"(r[1]), "=r"(r[2]), "=r"(r[3]) : "r"(addr) : "memory");
}
__device__ __forceinline__ void ldm_x4_t(uint32_t* r, uint32_t addr) {
    asm volatile("ldmatrix.sync.aligned.m8n8.x4.trans.shared.b16 {%0,%1,%2,%3}, [%4];"
                 : "=r"(r[0]), "=r"(r[1]), "=r"(r[2]), "=r"(r[3]) : "r"(addr) : "memory");
}
__device__ __forceinline__ void mma_bf16(float* d, const uint32_t* a, uint32_t b0, uint32_t b1) {
    asm volatile("mma.sync.aligned.m16n8k16.row.col.f32.bf16.bf16.f32 "
                 "{%0,%1,%2,%3}, {%4,%5,%6,%7}, {%8,%9}, {%0,%1,%2,%3};"
                 : "+f"(d[0]), "+f"(d[1]), "+f"(d[2]), "+f"(d[3])
                 : "r"(a[0]), "r"(a[1]), "r"(a[2]), "r"(a[3]), "r"(b0), "r"(b1));
}
__device__ __forceinline__ void mma_f16(float* d, const uint32_t* a, uint32_t b0, uint32_t b1) {
    asm volatile("mma.sync.aligned.m16n8k16.row.col.f32.f16.f16.f32 "
                 "{%0,%1,%2,%3}, {%4,%5,%6,%7}, {%8,%9}, {%0,%1,%2,%3};"
                 : "+f"(d[0]), "+f"(d[1]), "+f"(d[2]), "+f"(d[3])
                 : "r"(a[0]), "r"(a[1]), "r"(a[2]), "r"(a[3]), "r"(b0), "r"(b1));
}

// ---------------- pre-pass: K -> split-bf16, V -> fp16 ----------------
__global__ void __launch_bounds__(256) prepass(const float* __restrict__ x2,
                                               const float* __restrict__ x3) {
    size_t i4 = (size_t)blockIdx.x * blockDim.x + threadIdx.x;   // over NEL/4
    if (i4 >= NEL / 4) return;
    size_t i = i4 * 4;

    float4 k = reinterpret_cast<const float4*>(x2)[i4];
    float4 v = reinterpret_cast<const float4*>(x3)[i4];

    float ka[4] = {k.x, k.y, k.z, k.w};
    float va[4] = {v.x, v.y, v.z, v.w};
    __nv_bfloat16 kh[4], kl[4];
    __half vh[4];
    #pragma unroll
    for (int j = 0; j < 4; j++) {
        kh[j] = __float2bfloat16(ka[j]);
        kl[j] = __float2bfloat16(ka[j] - __bfloat162float(kh[j]));
        vh[j] = __float2half(va[j]);
    }
    *reinterpret_cast<uint2*>(g_Khi + i) = *reinterpret_cast<uint2*>(kh);
    *reinterpret_cast<uint2*>(g_Klo + i) = *reinterpret_cast<uint2*>(kl);
    *reinterpret_cast<uint2*>(g_Vh  + i) = *reinterpret_cast<uint2*>(vh);
}

// ---------------- fused flash-attention, deep-acc-distance MMA ----------------
__global__ void __launch_bounds__(256, 1)
fa_fwd(const float* __restrict__ x1, const float* __restrict__ sfp,
       float* __restrict__ out) {
    extern __shared__ char smem[];
    const uint32_t sb = smem_u32(smem);
    const int tid  = threadIdx.x;
    const int w    = tid >> 5;
    const int lane = tid & 31;
    const int b  = blockIdx.x >> 4;   // 16 q-tiles of 128 rows per batch
    const int qt = blockIdx.x & 15;
    const float sf = *sfp;

    // per-lane ldmatrix offsets (row stride ROWB, 16B chunks)
    const uint32_t k_lane = (uint32_t)((((lane >> 4) & 1) * 8 + (lane & 7)) * ROWB + ((lane >> 3) & 1) * 16);
    const uint32_t v_lane = (uint32_t)((((lane >> 3) & 1) * 8 + (lane & 7)) * ROWB + ((lane >> 4) & 1) * 16);

    // ---- load Q rows (fp32), scale, split into bf16 hi/lo a-frags ----
    const int r0 = lane >> 2, c0 = (lane & 3) * 2;
    const size_t qbase = ((size_t)b * SEQ + (size_t)qt * 128 + w * 16) * DIM;
    uint32_t qhi[32], qlo[32];
    #pragma unroll
    for (int kk = 0; kk < 8; kk++) {
        const size_t o00 = qbase + (size_t)r0 * DIM + kk * 16 + c0;
        #pragma unroll
        for (int p = 0; p < 4; p++) {
            const size_t off = o00 + (size_t)(p & 1) * 8 * DIM + (size_t)(p >> 1) * 8;
            float2 v = *reinterpret_cast<const float2*>(x1 + off);
            v.x *= sf; v.y *= sf;
            __nv_bfloat16 hx = __float2bfloat16(v.x), hy = __float2bfloat16(v.y);
            __nv_bfloat162 th; th.x = hx; th.y = hy;
            __nv_bfloat162 tl = __floats2bfloat162_rn(v.x - __bfloat162float(hx),
                                                      v.y - __bfloat162float(hy));
            qhi[kk*4+p] = *reinterpret_cast<uint32_t*>(&th);
            qlo[kk*4+p] = *reinterpret_cast<uint32_t*>(&tl);
        }
    }

    // ---- cp.async tile loader (256 threads) ----
    const size_t kvbase = (size_t)b * SEQ * DIM;
    auto load_tiles = [&](int stage, int kt) {
        const uint32_t s0 = sb + (uint32_t)stage * STAGE_B;
        const size_t g0 = kvbase + (size_t)kt * BLK_N * DIM;
        #pragma unroll
        for (int t = 0; t < 4; t++) {
            int c = tid + t * 256;               // 0..1023
            int row = c >> 4, col = c & 15;
            uint32_t so = (uint32_t)row * ROWB + (uint32_t)col * 16;
            size_t  go = g0 + (size_t)row * DIM + col * 8;
            CP16(s0 +            so, g_Khi + go);
            CP16(s0 + TILE_B   + so, g_Klo + go);
            CP16(s0 + 2*TILE_B + so, g_Vh  + go);
        }
    };

    float o[64];
    #pragma unroll
    for (int j = 0; j < 64; j++) o[j] = 0.0f;
    float m0 = -1e30f, m1 = -1e30f, l0 = 0.0f, l1 = 0.0f;
    float pa0 = 0.0f, pa1 = 0.0f;      // alpha from previous softmax
    float s[32];
    uint32_t pf[16];

    // ---- S = Qhi*Khi + Qhi*Klo + Qlo*Khi ----
    // Per kk: preload 4 ng B-frags, then sweep 8 distinct accumulator groups
    // per term -> same-acc reuse distance 8 (covers HMMA latency).
    auto do_qk = [&](int stage) {
        const uint32_t st = sb + (uint32_t)stage * STAGE_B;
        const uint32_t aKhi = st + k_lane;
        const uint32_t aKlo = st + TILE_B + k_lane;
        #pragma unroll
        for (int j = 0; j < 32; j++) s[j] = 0.0f;
        #pragma unroll
        for (int kk = 0; kk < 8; kk++) {
            uint32_t kb[16];
            #pragma unroll
            for (int ng = 0; ng < 4; ng++)
                ldm_x4(kb + 4*ng, aKhi + (uint32_t)ng * 16 * ROWB + (uint32_t)kk * 32);
            #pragma unroll
            for (int ng = 0; ng < 4; ng++) {           // term: Qhi*Khi (8 distinct accs)
                mma_bf16(s + (2*ng)   * 4, qhi + kk*4, kb[4*ng+0], kb[4*ng+1]);
                mma_bf16(s + (2*ng+1) * 4, qhi + kk*4, kb[4*ng+2], kb[4*ng+3]);
            }
            #pragma unroll
            for (int ng = 0; ng < 4; ng++) {           // term: Qlo*Khi
                mma_bf16(s + (2*ng)   * 4, qlo + kk*4, kb[4*ng+0], kb[4*ng+1]);
                mma_bf16(s + (2*ng+1) * 4, qlo + kk*4, kb[4*ng+2], kb[4*ng+3]);
            }
            #pragma unroll
            for (int ng = 0; ng < 4; ng++)
                ldm_x4(kb + 4*ng, aKlo + (uint32_t)ng * 16 * ROWB + (uint32_t)kk * 32);
            #pragma unroll
            for (int ng = 0; ng < 4; ng++) {           // term: Qhi*Klo
                mma_bf16(s + (2*ng)   * 4, qhi + kk*4, kb[4*ng+0], kb[4*ng+1]);
                mma_bf16(s + (2*ng+1) * 4, qhi + kk*4, kb[4*ng+2], kb[4*ng+3]);
            }
        }
    };

    // ---- O += P(prev) * V(stage): preload 4 dg V-frags, then 8-acc sweep ----
    auto do_pv = [&](int stage) {
        const uint32_t aV = sb + (uint32_t)stage * STAGE_B + 2 * TILE_B + v_lane;
        #pragma unroll
        for (int kk = 0; kk < 4; kk++) {
            #pragma unroll
            for (int dh = 0; dh < 2; dh++) {           // dg in two halves of 4
                uint32_t vb[16];
                #pragma unroll
                for (int dg = 0; dg < 4; dg++)
                    ldm_x4_t(vb + 4*dg, aV + (uint32_t)kk * 16 * ROWB + (uint32_t)(dh*4+dg) * 32);
                #pragma unroll
                for (int dg = 0; dg < 4; dg++) {       // 8 distinct acc groups
                    mma_f16(o + (2*(dh*4+dg))   * 4, pf + kk*4, vb[4*dg+0], vb[4*dg+1]);
                    mma_f16(o + (2*(dh*4+dg)+1) * 4, pf + kk*4, vb[4*dg+2], vb[4*dg+3]);
                }
            }
        }
    };

    // ---- online softmax on s -> pf, update m/l, set pa ----
    auto do_softmax = [&]() {
        float mx0 = -1e30f, mx1 = -1e30f;
        #pragma unroll
        for (int j = 0; j < 8; j++) {
            mx0 = fmaxf(mx0, fmaxf(s[j*4+0], s[j*4+1]));
            mx1 = fmaxf(mx1, fmaxf(s[j*4+2], s[j*4+3]));
        }
        mx0 = fmaxf(mx0, __shfl_xor_sync(0xffffffffu, mx0, 1));
        mx0 = fmaxf(mx0, __shfl_xor_sync(0xffffffffu, mx0, 2));
        mx1 = fmaxf(mx1, __shfl_xor_sync(0xffffffffu, mx1, 1));
        mx1 = fmaxf(mx1, __shfl_xor_sync(0xffffffffu, mx1, 2));
        const float mn0 = fmaxf(m0, mx0), mn1 = fmaxf(m1, mx1);
        const float a0 = __expf(m0 - mn0), a1 = __expf(m1 - mn1);
        m0 = mn0; m1 = mn1;

        float rs0 = 0.0f, rs1 = 0.0f;
        #pragma unroll
        for (int j = 0; j < 8; j++) {
            float p0 = __expf(s[j*4+0] - mn0);
            float p1 = __expf(s[j*4+1] - mn0);
            float p2 = __expf(s[j*4+2] - mn1);
            float p3 = __expf(s[j*4+3] - mn1);
            rs0 += p0 + p1; rs1 += p2 + p3;
            __half2 h01 = __floats2half2_rn(p0, p1);
            __half2 h23 = __floats2half2_rn(p2, p3);
            pf[(j >> 1) * 4 + (j & 1) * 2 + 0] = *reinterpret_cast<uint32_t*>(&h01);
            pf[(j >> 1) * 4 + (j & 1) * 2 + 1] = *reinterpret_cast<uint32_t*>(&h23);
        }
        l0 = l0 * a0 + rs0;
        l1 = l1 * a1 + rs1;
        pa0 = a0; pa1 = a1;
    };

    // ---- prologue: prefetch 2 stages, first QK + softmax ----
    load_tiles(0, 0); CP_COMMIT();
    load_tiles(1, 1); CP_COMMIT();
    CP_WAIT1();
    __syncthreads();
    do_qk(0);
    do_softmax();          // pa = 0 path: m was -inf, O is zero anyway
    __syncthreads();

    // ---- main loop: QK(kt) and PV(kt-1) back-to-back; softmax(kt) trails ----
    #pragma unroll 1
    for (int kt = 1; kt < NIT; kt++) {
        if (kt + 1 < NIT) { load_tiles((kt + 1) % 3, kt + 1); CP_COMMIT(); CP_WAIT1(); }
        else              { CP_WAIT0(); }
        __syncthreads();

        do_qk(kt % 3);                       // 192 HMMA, acc distance 8
        #pragma unroll
        for (int j = 0; j < 16; j++) {       // O *= alpha(kt-1)
            o[j*4+0] *= pa0; o[j*4+1] *= pa0;
            o[j*4+2] *= pa1; o[j*4+3] *= pa1;
        }
        do_pv((kt - 1) % 3);                 // 64 HMMA
        do_softmax();                        // gap hidden by sibling warp's burst

        __syncthreads();                     // V(kt-1) fully read before load(kt+2)
    }

    // ---- epilogue: last PV, normalize, store ----
    #pragma unroll
    for (int j = 0; j < 16; j++) {
        o[j*4+0] *= pa0; o[j*4+1] *= pa0;
        o[j*4+2] *= pa1; o[j*4+3] *= pa1;
    }
    do_pv((NIT - 1) % 3);

    l0 += __shfl_xor_sync(0xffffffffu, l0, 1);
    l0 += __shfl_xor_sync(0xffffffffu, l0, 2);
    l1 += __shfl_xor_sync(0xffffffffu, l1, 1);
    l1 += __shfl_xor_sync(0xffffffffu, l1, 2);
    const float i0 = 1.0f / l0, i1 = 1.0f / l1;

    const size_t row0 = (size_t)b * SEQ + (size_t)qt * 128 + w * 16 + r0;
    float* out0 = out + row0 * DIM + c0;
    float* out1 = out + (row0 + 8) * DIM + c0;
    #pragma unroll
    for (int j = 0; j < 16; j++) {
        float2 w0 = make_float2(o[j*4+0] * i0, o[j*4+1] * i0);
        float2 w1 = make_float2(o[j*4+2] * i1, o[j*4+3] * i1);
        *reinterpret_cast<float2*>(out0 + j * 8) = w0;
        *reinterpret_cast<float2*>(out1 + j * 8) = w1;
    }
}

// ---------------- launch ----------------
extern "C" void kernel_launch(void* const* d_in, const int* in_sizes, int n_in,
                              void* d_out, int out_size) {
    (void)in_sizes; (void)n_in; (void)out_size;
    const float* x1  = (const float*)d_in[0];
    const float* x2  = (const float*)d_in[1];
    const float* x3  = (const float*)d_in[2];
    const float* sfp = (const float*)d_in[4];
    float* out = (float*)d_out;

    cudaFuncSetAttribute(fa_fwd, cudaFuncAttributeMaxDynamicSharedMemorySize, SMEM_BYTES);

    prepass<<<(int)((NEL / 4 + 255) / 256), 256>>>(x2, x3);
    fa_fwd<<<NB * (SEQ / 128), 256, SMEM_BYTES>>>(x1, sfp, out);
}

// round 8
// speedup vs baseline: 1.0335x; 1.0335x over previous
#include <cuda_runtime.h>
#include <cuda_bf16.h>
#include <cuda_fp16.h>
#include <cstdint>

// ---------------- problem constants ----------------
static constexpr int NB  = 16;
static constexpr int SEQ = 2048;
static constexpr int DIM = 128;
static constexpr size_t NEL = (size_t)NB * SEQ * DIM;   // 4,194,304

// BLOCK_M=128 (8 warps x 16 rows), BLOCK_N=64, 32 iters, 2-stage ring
static constexpr int BLK_N   = 64;
static constexpr int NIT     = SEQ / BLK_N;             // 32
static constexpr uint32_t ROWB    = 272;                // 256B data + 16B pad (conflict-free ldmatrix)
static constexpr uint32_t TILE_B  = 64 * ROWB;          // 17408
static constexpr uint32_t STAGE_B = 3 * TILE_B;         // Khi, Klo, Vh = 52224
// smem: Qhi[128 x ROWB] + Qlo[128 x ROWB] + 2-stage ring
static constexpr uint32_t QTILE_B = 128 * ROWB;         // 34816
static constexpr uint32_t SM_QHI  = 0;
static constexpr uint32_t SM_QLO  = QTILE_B;
static constexpr uint32_t SM_RING = 2 * QTILE_B;        // 69632
static constexpr uint32_t SMEM_BYTES = SM_RING + 2 * STAGE_B;  // 174080

// ---------------- static device scratch (no allocs) ----------------
__device__ __align__(256) __nv_bfloat16 g_Khi[NEL];
__device__ __align__(256) __nv_bfloat16 g_Klo[NEL];
__device__ __align__(256) __half        g_Vh [NEL];

// ---------------- PTX helpers (base compute_103) ----------------
__device__ __forceinline__ uint32_t smem_u32(const void* p) {
    uint32_t a;
    asm("{ .reg .u64 t; cvta.to.shared.u64 t, %1; cvt.u32.u64 %0, t; }" : "=r"(a) : "l"(p));
    return a;
}
#define CP16(sm, gp) asm volatile("cp.async.cg.shared.global [%0], [%1], 16;" :: "r"(sm), "l"(gp))
#define CP_COMMIT()  asm volatile("cp.async.commit_group;" ::: "memory")
#define CP_WAIT1()   asm volatile("cp.async.wait_group 1;" ::: "memory")
#define CP_WAIT0()   asm volatile("cp.async.wait_group 0;" ::: "memory")

__device__ __forceinline__ void ldm_x4(uint32_t* r, uint32_t addr) {
    asm volatile("ldmatrix.sync.aligned.m8n8.x4.shared.b16 {%0,%1,%2,%3}, [%4];"
                 : "=r"(r[0]), "=r"(r[1]), "=r"(r[2]), "=r"(r[3]) : "r"(addr) : "memory");
}
__device__ __forceinline__ void ldm_x4_t(uint32_t* r, uint32_t addr) {
    asm volatile("ldmatrix.sync.aligned.m8n8.x4.trans.shared.b16 {%0,%1,%2,%3}, [%4];"
                 : "=r"(r[0]), "=r"(r[1]), "=r"(r[2]), "=r"(r[3]) : "r"(addr) : "memory");
}
__device__ __forceinline__ void mma_bf16(float* d, const uint32_t* a, uint32_t b0, uint32_t b1) {
    asm volatile("mma.sync.aligned.m16n8k16.row.col.f32.bf16.bf16.f32 "
                 "{%0,%1,%2,%3}, {%4,%5,%6,%7}, {%8,%9}, {%0,%1,%2,%3};"
                 : "+f"(d[0]), "+f"(d[1]), "+f"(d[2]), "+f"(d[3])
                 : "r"(a[0]), "r"(a[1]), "r"(a[2]), "r"(a[3]), "r"(b0), "r"(b1));
}
__device__ __forceinline__ void mma_f16(float* d, const uint32_t* a, uint32_t b0, uint32_t b1) {
    asm volatile("mma.sync.aligned.m16n8k16.row.col.f32.f16.f16.f32 "
                 "{%0,%1,%2,%3}, {%4,%5,%6,%7}, {%8,%9}, {%0,%1,%2,%3};"
                 : "+f"(d[0]), "+f"(d[1]), "+f"(d[2]), "+f"(d[3])
                 : "r"(a[0]), "r"(a[1]), "r"(a[2]), "r"(a[3]), "r"(b0), "r"(b1));
}

// ---------------- pre-pass: K -> split-bf16, V -> fp16 ----------------
__global__ void __launch_bounds__(256) prepass(const float* __restrict__ x2,
                                               const float* __restrict__ x3) {
    size_t i4 = (size_t)blockIdx.x * blockDim.x + threadIdx.x;   // over NEL/4
    if (i4 >= NEL / 4) return;
    size_t i = i4 * 4;

    float4 k = reinterpret_cast<const float4*>(x2)[i4];
    float4 v = reinterpret_cast<const float4*>(x3)[i4];

    float ka[4] = {k.x, k.y, k.z, k.w};
    float va[4] = {v.x, v.y, v.z, v.w};
    __nv_bfloat16 kh[4], kl[4];
    __half vh[4];
    #pragma unroll
    for (int j = 0; j < 4; j++) {
        kh[j] = __float2bfloat16(ka[j]);
        kl[j] = __float2bfloat16(ka[j] - __bfloat162float(kh[j]));
        vh[j] = __float2half(va[j]);
    }
    *reinterpret_cast<uint2*>(g_Khi + i) = *reinterpret_cast<uint2*>(kh);
    *reinterpret_cast<uint2*>(g_Klo + i) = *reinterpret_cast<uint2*>(kl);
    *reinterpret_cast<uint2*>(g_Vh  + i) = *reinterpret_cast<uint2*>(vh);
}

// ---------------- fused flash-attention, low-register (Q in SMEM) ----------------
__global__ void __launch_bounds__(256, 1)
fa_fwd(const float* __restrict__ x1, const float* __restrict__ sfp,
       float* __restrict__ out) {
    extern __shared__ char smem[];
    const uint32_t sb = smem_u32(smem);
    const uint32_t rb = sb + SM_RING;
    const int tid  = threadIdx.x;
    const int w    = tid >> 5;
    const int lane = tid & 31;
    const int b  = blockIdx.x >> 4;   // 16 q-tiles of 128 rows per batch
    const int qt = blockIdx.x & 15;
    const float sf = *sfp;

    // per-lane ldmatrix offsets (row stride ROWB, 16B chunks)
    const uint32_t k_lane = (uint32_t)((((lane >> 4) & 1) * 8 + (lane & 7)) * ROWB + ((lane >> 3) & 1) * 16);
    const uint32_t v_lane = (uint32_t)((((lane >> 3) & 1) * 8 + (lane & 7)) * ROWB + ((lane >> 4) & 1) * 16);
    // A-frag ldmatrix address: rows 0..15 by (lane&15), k-half by (lane>>4)
    const uint32_t q_lane = (uint32_t)((lane & 15) * ROWB + (lane >> 4) * 16)
                          + (uint32_t)(w * 16) * ROWB;   // warp's 16-row slice

    // ---- stage Q block into SMEM: fp32 -> scaled split bf16 hi/lo ----
    {
        const size_t qg = ((size_t)b * SEQ + (size_t)qt * 128) * DIM;
        #pragma unroll
        for (int i = tid; i < 128 * 64; i += 256) {       // float2 chunks
            int row = i >> 6, c2 = (i & 63) * 2;
            float2 v = *reinterpret_cast<const float2*>(x1 + qg + (size_t)row * DIM + c2);
            v.x *= sf; v.y *= sf;
            __nv_bfloat16 hx = __float2bfloat16(v.x), hy = __float2bfloat16(v.y);
            __nv_bfloat162 th; th.x = hx; th.y = hy;
            __nv_bfloat162 tl = __floats2bfloat162_rn(v.x - __bfloat162float(hx),
                                                      v.y - __bfloat162float(hy));
            uint32_t soff = (uint32_t)row * ROWB + (uint32_t)c2 * 2;
            *reinterpret_cast<uint32_t*>(smem + SM_QHI + soff) = *reinterpret_cast<uint32_t*>(&th);
            *reinterpret_cast<uint32_t*>(smem + SM_QLO + soff) = *reinterpret_cast<uint32_t*>(&tl);
        }
    }

    // ---- cp.async tile loader (256 threads) ----
    const size_t kvbase = (size_t)b * SEQ * DIM;
    auto load_tiles = [&](int stage, int kt) {
        const uint32_t s0 = rb + (uint32_t)stage * STAGE_B;
        const size_t g0 = kvbase + (size_t)kt * BLK_N * DIM;
        #pragma unroll
        for (int t = 0; t < 4; t++) {
            int c = tid + t * 256;               // 0..1023
            int row = c >> 4, col = c & 15;
            uint32_t so = (uint32_t)row * ROWB + (uint32_t)col * 16;
            size_t  go = g0 + (size_t)row * DIM + col * 8;
            CP16(s0 +            so, g_Khi + go);
            CP16(s0 + TILE_B   + so, g_Klo + go);
            CP16(s0 + 2*TILE_B + so, g_Vh  + go);
        }
    };

    float o[64];
    #pragma unroll
    for (int j = 0; j < 64; j++) o[j] = 0.0f;
    float m0 = -1e30f, m1 = -1e30f, l0 = 0.0f, l1 = 0.0f;
    float s[32];
    uint32_t pf[16];

    const int r0 = lane >> 2, c0 = (lane & 3) * 2;

    load_tiles(0, 0); CP_COMMIT();

    #pragma unroll 1
    for (int kt = 0; kt < NIT; kt++) {
        if (kt + 1 < NIT) { load_tiles((kt + 1) & 1, kt + 1); CP_COMMIT(); CP_WAIT1(); }
        else              { CP_WAIT0(); }
        __syncthreads();

        const uint32_t st = rb + (uint32_t)(kt & 1) * STAGE_B;
        const uint32_t aKhi = st + k_lane;
        const uint32_t aKlo = st + TILE_B + k_lane;
        const uint32_t aV   = st + 2 * TILE_B + v_lane;

        // ---- S = Qhi*Khi + Qlo*Khi + Qhi*Klo (Q frags streamed from SMEM) ----
        #pragma unroll
        for (int j = 0; j < 32; j++) s[j] = 0.0f;
        #pragma unroll
        for (int kk = 0; kk < 8; kk++) {
            uint32_t qh[4], ql[4];
            ldm_x4(qh, sb + SM_QHI + q_lane + (uint32_t)kk * 32);
            ldm_x4(ql, sb + SM_QLO + q_lane + (uint32_t)kk * 32);
            #pragma unroll
            for (int half = 0; half < 2; half++) {
                uint32_t kb[8];
                ldm_x4(kb,     aKhi + (uint32_t)(half*2+0) * 16 * ROWB + (uint32_t)kk * 32);
                ldm_x4(kb + 4, aKhi + (uint32_t)(half*2+1) * 16 * ROWB + (uint32_t)kk * 32);
                mma_bf16(s + (4*half)     * 4, qh, kb[0], kb[1]);
                mma_bf16(s + (4*half + 1) * 4, qh, kb[2], kb[3]);
                mma_bf16(s + (4*half + 2) * 4, qh, kb[4], kb[5]);
                mma_bf16(s + (4*half + 3) * 4, qh, kb[6], kb[7]);
                mma_bf16(s + (4*half)     * 4, ql, kb[0], kb[1]);
                mma_bf16(s + (4*half + 1) * 4, ql, kb[2], kb[3]);
                mma_bf16(s + (4*half + 2) * 4, ql, kb[4], kb[5]);
                mma_bf16(s + (4*half + 3) * 4, ql, kb[6], kb[7]);
            }
            #pragma unroll
            for (int half = 0; half < 2; half++) {
                uint32_t kb[8];
                ldm_x4(kb,     aKlo + (uint32_t)(half*2+0) * 16 * ROWB + (uint32_t)kk * 32);
                ldm_x4(kb + 4, aKlo + (uint32_t)(half*2+1) * 16 * ROWB + (uint32_t)kk * 32);
                mma_bf16(s + (4*half)     * 4, qh, kb[0], kb[1]);
                mma_bf16(s + (4*half + 1) * 4, qh, kb[2], kb[3]);
                mma_bf16(s + (4*half + 2) * 4, qh, kb[4], kb[5]);
                mma_bf16(s + (4*half + 3) * 4, qh, kb[6], kb[7]);
            }
        }

        // ---- online softmax (rows r0 and r0+8; quad lanes share a row) ----
        float mx0 = -1e30f, mx1 = -1e30f;
        #pragma unroll
        for (int j = 0; j < 8; j++) {
            mx0 = fmaxf(mx0, fmaxf(s[j*4+0], s[j*4+1]));
            mx1 = fmaxf(mx1, fmaxf(s[j*4+2], s[j*4+3]));
        }
        mx0 = fmaxf(mx0, __shfl_xor_sync(0xffffffffu, mx0, 1));
        mx0 = fmaxf(mx0, __shfl_xor_sync(0xffffffffu, mx0, 2));
        mx1 = fmaxf(mx1, __shfl_xor_sync(0xffffffffu, mx1, 1));
        mx1 = fmaxf(mx1, __shfl_xor_sync(0xffffffffu, mx1, 2));
        const float mn0 = fmaxf(m0, mx0), mn1 = fmaxf(m1, mx1);
        const float a0 = __expf(m0 - mn0), a1 = __expf(m1 - mn1);
        m0 = mn0; m1 = mn1;

        float rs0 = 0.0f, rs1 = 0.0f;
        #pragma unroll
        for (int j = 0; j < 8; j++) {
            float p0 = __expf(s[j*4+0] - mn0);
            float p1 = __expf(s[j*4+1] - mn0);
            float p2 = __expf(s[j*4+2] - mn1);
            float p3 = __expf(s[j*4+3] - mn1);
            rs0 += p0 + p1; rs1 += p2 + p3;
            __half2 h01 = __floats2half2_rn(p0, p1);
            __half2 h23 = __floats2half2_rn(p2, p3);
            pf[(j >> 1) * 4 + (j & 1) * 2 + 0] = *reinterpret_cast<uint32_t*>(&h01);
            pf[(j >> 1) * 4 + (j & 1) * 2 + 1] = *reinterpret_cast<uint32_t*>(&h23);
        }
        l0 = l0 * a0 + rs0;
        l1 = l1 * a1 + rs1;

        #pragma unroll
        for (int j = 0; j < 16; j++) {
            o[j*4+0] *= a0; o[j*4+1] *= a0;
            o[j*4+2] *= a1; o[j*4+3] *= a1;
        }

        // ---- O += P * V (fp16) ----
        #pragma unroll
        for (int kk = 0; kk < 4; kk++) {
            #pragma unroll
            for (int dh = 0; dh < 4; dh++) {          // pairs of dg
                uint32_t vb[8];
                ldm_x4_t(vb,     aV + (uint32_t)kk * 16 * ROWB + (uint32_t)(dh*2+0) * 32);
                ldm_x4_t(vb + 4, aV + (uint32_t)kk * 16 * ROWB + (uint32_t)(dh*2+1) * 32);
                mma_f16(o + (2*(dh*2+0))   * 4, pf + kk*4, vb[0], vb[1]);
                mma_f16(o + (2*(dh*2+0)+1) * 4, pf + kk*4, vb[2], vb[3]);
                mma_f16(o + (2*(dh*2+1))   * 4, pf + kk*4, vb[4], vb[5]);
                mma_f16(o + (2*(dh*2+1)+1) * 4, pf + kk*4, vb[6], vb[7]);
            }
        }
        __syncthreads();
    }

    // ---- finalize: full row sums over quad, normalize, store ----
    l0 += __shfl_xor_sync(0xffffffffu, l0, 1);
    l0 += __shfl_xor_sync(0xffffffffu, l0, 2);
    l1 += __shfl_xor_sync(0xffffffffu, l1, 1);
    l1 += __shfl_xor_sync(0xffffffffu, l1, 2);
    const float i0 = 1.0f / l0, i1 = 1.0f / l1;

    const size_t row0 = (size_t)b * SEQ + (size_t)qt * 128 + w * 16 + r0;
    float* out0 = out + row0 * DIM + c0;
    float* out1 = out + (row0 + 8) * DIM + c0;
    #pragma unroll
    for (int j = 0; j < 16; j++) {
        float2 w0 = make_float2(o[j*4+0] * i0, o[j*4+1] * i0);
        float2 w1 = make_float2(o[j*4+2] * i1, o[j*4+3] * i1);
        *reinterpret_cast<float2*>(out0 + j * 8) = w0;
        *reinterpret_cast<float2*>(out1 + j * 8) = w1;
    }
}

// ---------------- launch ----------------
extern "C" void kernel_launch(void* const* d_in, const int* in_sizes, int n_in,
                              void* d_out, int out_size) {
    (void)in_sizes; (void)n_in; (void)out_size;
    const float* x1  = (const float*)d_in[0];
    const float* x2  = (const float*)d_in[1];
    const float* x3  = (const float*)d_in[2];
    const float* sfp = (const float*)d_in[4];
    float* out = (float*)d_out;

    cudaFuncSetAttribute(fa_fwd, cudaFuncAttributeMaxDynamicSharedMemorySize, SMEM_BYTES);

    prepass<<<(int)((NEL / 4 + 255) / 256), 256>>>(x2, x3);
    fa_fwd<<<NB * (SEQ / 128), 256, SMEM_BYTES>>>(x1, sfp, out);
}